// round 5
// baseline (speedup 1.0000x reference)
#include <cuda_runtime.h>
#include <cuda_bf16.h>
#include <cstdint>

#define EPSF 1e-5f
#define QBF  127.0f

static constexpr int MTOK  = 4 * 4096;
static constexpr int DIN   = 1024;
static constexpr int INNER = 4096;

// ---------------- device scratch ----------------
__device__ float g_wfac[2];
__device__ float g_part[2][256];
__device__ __align__(16) __nv_bfloat16 g_w1q[(size_t)INNER * DIN];
__device__ __align__(16) __nv_bfloat16 g_w2q[(size_t)DIN * INNER];
__device__ __align__(16) __nv_bfloat16 g_xq [(size_t)MTOK * DIN];
__device__ float g_sx[MTOK];
__device__ __align__(16) float g_h [(size_t)MTOK * INNER];
__device__ __align__(16) __nv_bfloat16 g_hq[(size_t)MTOK * INNER];
__device__ float g_sh[MTOK];

// ---------------- helpers ----------------
__device__ __forceinline__ uint32_t smem_u32(const void* p) {
    uint32_t a;
    asm("{ .reg .u64 t; cvta.to.shared.u64 t, %1; cvt.u32.u64 %0, t; }" : "=r"(a) : "l"(p));
    return a;
}
__device__ __forceinline__ void cp_async16(uint32_t dst, const void* src) {
    asm volatile("cp.async.cg.shared.global [%0], [%1], 16;" :: "r"(dst), "l"(src) : "memory");
}
#define CP_COMMIT()  asm volatile("cp.async.commit_group;" ::: "memory")
#define CP_WAIT(N)   asm volatile("cp.async.wait_group %0;" :: "n"(N) : "memory")

__device__ __forceinline__ void ldmx4(uint32_t& r0, uint32_t& r1, uint32_t& r2, uint32_t& r3,
                                      uint32_t addr) {
    asm volatile("ldmatrix.sync.aligned.m8n8.x4.shared.b16 {%0,%1,%2,%3}, [%4];"
                 : "=r"(r0), "=r"(r1), "=r"(r2), "=r"(r3) : "r"(addr));
}
__device__ __forceinline__ void mma_bf16(float* c, const uint32_t* a, const uint32_t* b) {
    asm volatile("mma.sync.aligned.m16n8k16.row.col.f32.bf16.bf16.f32 "
                 "{%0,%1,%2,%3}, {%4,%5,%6,%7}, {%8,%9}, {%0,%1,%2,%3};"
                 : "+f"(c[0]), "+f"(c[1]), "+f"(c[2]), "+f"(c[3])
                 : "r"(a[0]), "r"(a[1]), "r"(a[2]), "r"(a[3]), "r"(b[0]), "r"(b[1]));
}

// ---------------- weight absmean partials (both weights) -----------------
__global__ void wabs_part(const float* __restrict__ w1, const float* __restrict__ w2,
                          int n) {
    int slot = blockIdx.y;
    const float4* w4 = (const float4*)(slot ? w2 : w1);
    int nv = n >> 2;
    float s = 0.f;
    for (int i = blockIdx.x * blockDim.x + threadIdx.x; i < nv; i += gridDim.x * blockDim.x) {
        float4 v = w4[i];
        s += fabsf(v.x) + fabsf(v.y) + fabsf(v.z) + fabsf(v.w);
    }
    __shared__ float sh[256];
    sh[threadIdx.x] = s;
    __syncthreads();
    for (int o = 128; o > 0; o >>= 1) {
        if (threadIdx.x < o) sh[threadIdx.x] += sh[threadIdx.x + o];
        __syncthreads();
    }
    if (threadIdx.x == 0) g_part[slot][blockIdx.x] = sh[0];
}

// ---------------- ternary weight quant (inlines the final reduce) --------
__global__ void wquant(const float* __restrict__ w1, const float* __restrict__ w2, int n) {
    int slot = blockIdx.y;
    // every block redundantly reduces the 256 partials (deterministic, cheap)
    __shared__ float sh[256];
    sh[threadIdx.x] = g_part[slot][threadIdx.x];
    __syncthreads();
    for (int o = 128; o > 0; o >>= 1) {
        if (threadIdx.x < o) sh[threadIdx.x] += sh[threadIdx.x + o];
        __syncthreads();
    }
    float wf = fmaxf(sh[0] / (float)n, EPSF);
    if (blockIdx.x == 0 && threadIdx.x == 0) g_wfac[slot] = wf;

    const float* w = slot ? w2 : w1;
    __nv_bfloat16* q = slot ? g_w2q : g_w1q;
    int i = blockIdx.x * blockDim.x + threadIdx.x;
    int nv = n >> 2;
    if (i >= nv) return;
    float sc = 1.f / wf;
    float4 v = ((const float4*)w)[i];
    int t0 = (int)rintf(v.x * sc); t0 = t0 < -1 ? -1 : (t0 > 1 ? 1 : t0);
    int t1 = (int)rintf(v.y * sc); t1 = t1 < -1 ? -1 : (t1 > 1 ? 1 : t1);
    int t2 = (int)rintf(v.z * sc); t2 = t2 < -1 ? -1 : (t2 > 1 ? 1 : t2);
    int t3 = (int)rintf(v.w * sc); t3 = t3 < -1 ? -1 : (t3 > 1 ? 1 : t3);
    __nv_bfloat162* q2 = (__nv_bfloat162*)(q + (size_t)i * 4);
    q2[0] = __nv_bfloat162(__float2bfloat16_rn((float)t0), __float2bfloat16_rn((float)t1));
    q2[1] = __nv_bfloat162(__float2bfloat16_rn((float)t2), __float2bfloat16_rn((float)t3));
}

// ---------------- rmsnorm + absmax int8 quant, warp-per-row --------------
__device__ __forceinline__ uint32_t quant4(float4 f, float rn, float sc) {
    int t0 = (int)rintf((f.x * rn) * sc); t0 = t0 < -128 ? -128 : (t0 > 127 ? 127 : t0);
    int t1 = (int)rintf((f.y * rn) * sc); t1 = t1 < -128 ? -128 : (t1 > 127 ? 127 : t1);
    int t2 = (int)rintf((f.z * rn) * sc); t2 = t2 < -128 ? -128 : (t2 > 127 ? 127 : t2);
    int t3 = (int)rintf((f.w * rn) * sc); t3 = t3 < -128 ? -128 : (t3 > 127 ? 127 : t3);
    (void)t0; (void)t1; (void)t2; (void)t3;
    return 0; // unused
}

__global__ __launch_bounds__(256)
void act_quant(const float* __restrict__ xin, int slot) {
    const int lane = threadIdx.x & 31;
    const int wrow = blockIdx.x * 8 + (threadIdx.x >> 5);

    if (slot == 0) {
        // D = 1024: whole row in registers (8 float4/lane)
        const float4* xr = (const float4*)(xin + (size_t)wrow * DIN);
        float4 v[8];
        float ss = 0.f, am = 0.f;
#pragma unroll
        for (int i = 0; i < 8; i++) {
            float4 f = xr[lane + 32 * i];
            v[i] = f;
            ss += f.x * f.x + f.y * f.y + f.z * f.z + f.w * f.w;
            am = fmaxf(am, fmaxf(fmaxf(fabsf(f.x), fabsf(f.y)), fmaxf(fabsf(f.z), fabsf(f.w))));
        }
#pragma unroll
        for (int o = 16; o > 0; o >>= 1) {
            ss += __shfl_xor_sync(0xffffffffu, ss, o);
            am = fmaxf(am, __shfl_xor_sync(0xffffffffu, am, o));
        }
        float rn = rsqrtf(ss / (float)DIN + EPSF);
        float amn = fmaxf(am * rn, EPSF);
        float sc = QBF / amn;
        if (lane == 0) g_sx[wrow] = amn / QBF;

        uint2* qr = (uint2*)(g_xq + (size_t)wrow * DIN);
#pragma unroll
        for (int i = 0; i < 8; i++) {
            float4 f = v[i];
            int t0 = (int)rintf((f.x * rn) * sc); t0 = t0 < -128 ? -128 : (t0 > 127 ? 127 : t0);
            int t1 = (int)rintf((f.y * rn) * sc); t1 = t1 < -128 ? -128 : (t1 > 127 ? 127 : t1);
            int t2 = (int)rintf((f.z * rn) * sc); t2 = t2 < -128 ? -128 : (t2 > 127 ? 127 : t2);
            int t3 = (int)rintf((f.w * rn) * sc); t3 = t3 < -128 ? -128 : (t3 > 127 ? 127 : t3);
            __nv_bfloat162 p0(__float2bfloat16_rn((float)t0), __float2bfloat16_rn((float)t1));
            __nv_bfloat162 p1(__float2bfloat16_rn((float)t2), __float2bfloat16_rn((float)t3));
            uint2 u;
            u.x = *(uint32_t*)&p0;
            u.y = *(uint32_t*)&p1;
            qr[lane + 32 * i] = u;
        }
    } else {
        // D = 4096: two passes (second pass hits L1/L2)
        const float4* xr = (const float4*)(g_h + (size_t)wrow * INNER);
        float ss = 0.f, am = 0.f;
#pragma unroll 4
        for (int i = 0; i < 32; i++) {
            float4 f = xr[lane + 32 * i];
            ss += f.x * f.x + f.y * f.y + f.z * f.z + f.w * f.w;
            am = fmaxf(am, fmaxf(fmaxf(fabsf(f.x), fabsf(f.y)), fmaxf(fabsf(f.z), fabsf(f.w))));
        }
#pragma unroll
        for (int o = 16; o > 0; o >>= 1) {
            ss += __shfl_xor_sync(0xffffffffu, ss, o);
            am = fmaxf(am, __shfl_xor_sync(0xffffffffu, am, o));
        }
        float rn = rsqrtf(ss / (float)INNER + EPSF);
        float amn = fmaxf(am * rn, EPSF);
        float sc = QBF / amn;
        if (lane == 0) g_sh[wrow] = amn / QBF;

        uint2* qr = (uint2*)(g_hq + (size_t)wrow * INNER);
#pragma unroll 4
        for (int i = 0; i < 32; i++) {
            float4 f = xr[lane + 32 * i];
            int t0 = (int)rintf((f.x * rn) * sc); t0 = t0 < -128 ? -128 : (t0 > 127 ? 127 : t0);
            int t1 = (int)rintf((f.y * rn) * sc); t1 = t1 < -128 ? -128 : (t1 > 127 ? 127 : t1);
            int t2 = (int)rintf((f.z * rn) * sc); t2 = t2 < -128 ? -128 : (t2 > 127 ? 127 : t2);
            int t3 = (int)rintf((f.w * rn) * sc); t3 = t3 < -128 ? -128 : (t3 > 127 ? 127 : t3);
            __nv_bfloat162 p0(__float2bfloat16_rn((float)t0), __float2bfloat16_rn((float)t1));
            __nv_bfloat162 p1(__float2bfloat16_rn((float)t2), __float2bfloat16_rn((float)t3));
            uint2 u;
            u.x = *(uint32_t*)&p0;
            u.y = *(uint32_t*)&p1;
            qr[lane + 32 * i] = u;
        }
    }
}

// ---------------- bf16 HMMA GEMM: tile 128x128, K-stage 64 elems ----------
static constexpr int BM = 128, BN = 128, BKE = 64;            // BKE elems = 128 bytes
static constexpr int STAGE_BYTES = (BM + BN) * BKE * 2;       // 32 KB
static constexpr int SMEM_BYTES  = 2 * STAGE_BYTES;           // 64 KB

__device__ __forceinline__ uint32_t swz(uint32_t row, uint32_t kb) {
    return row * 128u + (kb ^ ((row & 7u) << 4));
}

__global__ __launch_bounds__(256, 2)
void gemm_bf16(const float* __restrict__ bias, float* __restrict__ dout, int layer) {
    const __nv_bfloat16 *A, *B;
    const float* inva;
    float* out;
    int N, K;
    if (layer == 0) { A = g_xq; B = g_w1q; inva = g_sx; out = g_h;  N = INNER; K = DIN;  }
    else            { A = g_hq; B = g_w2q; inva = g_sh; out = dout; N = DIN;   K = INNER; }

    extern __shared__ char smem[];
    const uint32_t sb = smem_u32(smem);

    const int tid = threadIdx.x;
    const int wid = tid >> 5, lid = tid & 31;
    const int wm = wid >> 1, wn = wid & 1;        // 4 x 2 warps, each 32m x 64n
    const int m0 = blockIdx.y * BM;
    const int n0 = blockIdx.x * BN;

    float acc[2][8][4];
#pragma unroll
    for (int i = 0; i < 2; i++)
#pragma unroll
        for (int j = 0; j < 8; j++)
#pragma unroll
            for (int q = 0; q < 4; q++) acc[i][j][q] = 0.f;

    const int nk = K / BKE;

    const int ltile = lid >> 3, lr = lid & 7;
    uint32_t a_off[2], a_xor[2];
    const uint32_t a_kadd = (ltile >> 1) * 16;
#pragma unroll
    for (int i = 0; i < 2; i++) {
        uint32_t row = wm * 32 + i * 16 + (ltile & 1) * 8 + lr;
        a_off[i] = row * 128u;
        a_xor[i] = (row & 7u) << 4;
    }
    uint32_t b_off[4], b_xor[4];
    const uint32_t b_kadd = (ltile & 1) * 16;
#pragma unroll
    for (int jb = 0; jb < 4; jb++) {
        uint32_t row = wn * 64 + jb * 16 + (ltile >> 1) * 8 + lr;
        b_off[jb] = row * 128u;
        b_xor[jb] = (row & 7u) << 4;
    }

    auto load_stage = [&](int buf, int c) {
        uint32_t baseA = sb + buf * STAGE_BYTES;
        uint32_t baseB = baseA + BM * BKE * 2;
        const __nv_bfloat16* Ap = A + (size_t)m0 * K + c * BKE;
        const __nv_bfloat16* Bp = B + (size_t)n0 * K + c * BKE;
#pragma unroll
        for (int t = 0; t < 4; t++) {
            int ci = tid + t * 256;
            uint32_t row = ci >> 3, ch = (ci & 7) * 16;
            cp_async16(baseA + swz(row, ch), Ap + (size_t)row * K + (ci & 7) * 8);
        }
#pragma unroll
        for (int t = 0; t < 4; t++) {
            int ci = tid + t * 256;
            uint32_t row = ci >> 3, ch = (ci & 7) * 16;
            cp_async16(baseB + swz(row, ch), Bp + (size_t)row * K + (ci & 7) * 8);
        }
        CP_COMMIT();
    };

    load_stage(0, 0);

    for (int c = 0; c < nk; c++) {
        if (c + 1 < nk) {
            load_stage((c + 1) & 1, c + 1);
            CP_WAIT(1);
        } else {
            CP_WAIT(0);
        }
        __syncthreads();

        uint32_t baseA = sb + (c & 1) * STAGE_BYTES;
        uint32_t baseB = baseA + BM * BKE * 2;

#pragma unroll
        for (int ks = 0; ks < 4; ks++) {
            uint32_t kbA = ks * 32 + a_kadd;
            uint32_t kbB = ks * 32 + b_kadd;
            uint32_t afr[2][4];
#pragma unroll
            for (int i = 0; i < 2; i++)
                ldmx4(afr[i][0], afr[i][1], afr[i][2], afr[i][3],
                      baseA + a_off[i] + (kbA ^ a_xor[i]));
            uint32_t bfr[8][2];
#pragma unroll
            for (int jb = 0; jb < 4; jb++) {
                uint32_t r0, r1, r2, r3;
                ldmx4(r0, r1, r2, r3, baseB + b_off[jb] + (kbB ^ b_xor[jb]));
                bfr[jb * 2 + 0][0] = r0; bfr[jb * 2 + 0][1] = r1;
                bfr[jb * 2 + 1][0] = r2; bfr[jb * 2 + 1][1] = r3;
            }
#pragma unroll
            for (int i = 0; i < 2; i++)
#pragma unroll
                for (int j = 0; j < 8; j++)
                    mma_bf16(acc[i][j], afr[i], bfr[j]);
        }
        __syncthreads();
    }

    const float fw = g_wfac[layer];
    const int g = lid >> 2, tig = lid & 3;
#pragma unroll
    for (int i = 0; i < 2; i++) {
        int r0 = m0 + wm * 32 + i * 16 + g;
        float fa0 = inva[r0] * fw;
        float fa1 = inva[r0 + 8] * fw;
#pragma unroll
        for (int j = 0; j < 8; j++) {
            int n = n0 + wn * 64 + j * 8 + tig * 2;
            float bx = bias[n], by = bias[n + 1];
            float v0 = acc[i][j][0] * fa0 + bx;
            float v1 = acc[i][j][1] * fa0 + by;
            float v2 = acc[i][j][2] * fa1 + bx;
            float v3 = acc[i][j][3] * fa1 + by;
            if (layer == 0) {
                v0 = 0.5f * v0 * (1.f + erff(v0 * 0.70710678118654752f));
                v1 = 0.5f * v1 * (1.f + erff(v1 * 0.70710678118654752f));
                v2 = 0.5f * v2 * (1.f + erff(v2 * 0.70710678118654752f));
                v3 = 0.5f * v3 * (1.f + erff(v3 * 0.70710678118654752f));
            }
            *(float2*)(out + (size_t)r0 * N + n)       = make_float2(v0, v1);
            *(float2*)(out + (size_t)(r0 + 8) * N + n) = make_float2(v2, v3);
        }
    }
}

// -------------------------------------------------------------------------
extern "C" void kernel_launch(void* const* d_in, const int* in_sizes, int n_in,
                              void* d_out, int out_size) {
    const float* x  = (const float*)d_in[0];
    const float* w1 = (const float*)d_in[1];
    const float* b1 = (const float*)d_in[2];
    const float* w2 = (const float*)d_in[3];
    const float* b2 = (const float*)d_in[4];
    float* out = (float*)d_out;

    const int n = INNER * DIN;

    cudaFuncSetAttribute(gemm_bf16, cudaFuncAttributeMaxDynamicSharedMemorySize, SMEM_BYTES);

    wabs_part<<<dim3(256, 2), 256>>>(w1, w2, n);                 // 0
    wquant<<<dim3(n / 4 / 256, 2), 256>>>(w1, w2, n);            // 1 (includes final reduce)
    act_quant<<<MTOK / 8, 256>>>(x, 0);                          // 2
    gemm_bf16<<<dim3(INNER / BN, MTOK / BM), 256, SMEM_BYTES>>>(b1, nullptr, 0);  // 3
    act_quant<<<MTOK / 8, 256>>>(nullptr, 1);                    // 4
    gemm_bf16<<<dim3(DIN / BN, MTOK / BM), 256, SMEM_BYTES>>>(b2, out, 1);        // 5
}

// round 6
// speedup vs baseline: 1.0347x; 1.0347x over previous
#include <cuda_runtime.h>
#include <cuda_bf16.h>
#include <cstdint>

#define EPSF 1e-5f
#define QBF  127.0f

static constexpr int MTOK  = 4 * 4096;
static constexpr int DIN   = 1024;
static constexpr int INNER = 4096;

// ---------------- device scratch ----------------
__device__ float g_wfac[2];
__device__ float g_part[2][256];
__device__ __align__(16) __nv_bfloat16 g_w1q[(size_t)INNER * DIN];
__device__ __align__(16) __nv_bfloat16 g_w2q[(size_t)DIN * INNER];
__device__ __align__(16) __nv_bfloat16 g_xq [(size_t)MTOK * DIN];
__device__ float g_sx[MTOK];
__device__ __align__(16) float g_h [(size_t)MTOK * INNER];
__device__ __align__(16) __nv_bfloat16 g_hq[(size_t)MTOK * INNER];
__device__ float g_sh[MTOK];
// per-(row, 64-col tile) partial stats of h, written by gemm1 epilogue
__device__ __align__(16) float g_hss[(size_t)MTOK * 64];
__device__ __align__(16) float g_ham[(size_t)MTOK * 64];

// ---------------- helpers ----------------
__device__ __forceinline__ uint32_t smem_u32(const void* p) {
    uint32_t a;
    asm("{ .reg .u64 t; cvta.to.shared.u64 t, %1; cvt.u32.u64 %0, t; }" : "=r"(a) : "l"(p));
    return a;
}
__device__ __forceinline__ void cp_async16(uint32_t dst, const void* src) {
    asm volatile("cp.async.cg.shared.global [%0], [%1], 16;" :: "r"(dst), "l"(src) : "memory");
}
#define CP_COMMIT()  asm volatile("cp.async.commit_group;" ::: "memory")
#define CP_WAIT(N)   asm volatile("cp.async.wait_group %0;" :: "n"(N) : "memory")

__device__ __forceinline__ void ldmx4(uint32_t& r0, uint32_t& r1, uint32_t& r2, uint32_t& r3,
                                      uint32_t addr) {
    asm volatile("ldmatrix.sync.aligned.m8n8.x4.shared.b16 {%0,%1,%2,%3}, [%4];"
                 : "=r"(r0), "=r"(r1), "=r"(r2), "=r"(r3) : "r"(addr));
}
__device__ __forceinline__ void mma_bf16(float* c, const uint32_t* a, const uint32_t* b) {
    asm volatile("mma.sync.aligned.m16n8k16.row.col.f32.bf16.bf16.f32 "
                 "{%0,%1,%2,%3}, {%4,%5,%6,%7}, {%8,%9}, {%0,%1,%2,%3};"
                 : "+f"(c[0]), "+f"(c[1]), "+f"(c[2]), "+f"(c[3])
                 : "r"(a[0]), "r"(a[1]), "r"(a[2]), "r"(a[3]), "r"(b[0]), "r"(b[1]));
}

// ---------------- weight absmean partials (both weights) -----------------
__global__ void wabs_part(const float* __restrict__ w1, const float* __restrict__ w2,
                          int n) {
    int slot = blockIdx.y;
    const float4* w4 = (const float4*)(slot ? w2 : w1);
    int nv = n >> 2;
    float s = 0.f;
    for (int i = blockIdx.x * blockDim.x + threadIdx.x; i < nv; i += gridDim.x * blockDim.x) {
        float4 v = w4[i];
        s += fabsf(v.x) + fabsf(v.y) + fabsf(v.z) + fabsf(v.w);
    }
    __shared__ float sh[256];
    sh[threadIdx.x] = s;
    __syncthreads();
    for (int o = 128; o > 0; o >>= 1) {
        if (threadIdx.x < o) sh[threadIdx.x] += sh[threadIdx.x + o];
        __syncthreads();
    }
    if (threadIdx.x == 0) g_part[slot][blockIdx.x] = sh[0];
}

// ---------------- ternary weight quant (inlines the final reduce) --------
__global__ void wquant(const float* __restrict__ w1, const float* __restrict__ w2, int n) {
    int slot = blockIdx.y;
    __shared__ float sh[256];
    sh[threadIdx.x] = g_part[slot][threadIdx.x];
    __syncthreads();
    for (int o = 128; o > 0; o >>= 1) {
        if (threadIdx.x < o) sh[threadIdx.x] += sh[threadIdx.x + o];
        __syncthreads();
    }
    float wf = fmaxf(sh[0] / (float)n, EPSF);
    if (blockIdx.x == 0 && threadIdx.x == 0) g_wfac[slot] = wf;

    const float* w = slot ? w2 : w1;
    __nv_bfloat16* q = slot ? g_w2q : g_w1q;
    int i = blockIdx.x * blockDim.x + threadIdx.x;
    int nv = n >> 2;
    if (i >= nv) return;
    float sc = 1.f / wf;
    float4 v = ((const float4*)w)[i];
    int t0 = (int)rintf(v.x * sc); t0 = t0 < -1 ? -1 : (t0 > 1 ? 1 : t0);
    int t1 = (int)rintf(v.y * sc); t1 = t1 < -1 ? -1 : (t1 > 1 ? 1 : t1);
    int t2 = (int)rintf(v.z * sc); t2 = t2 < -1 ? -1 : (t2 > 1 ? 1 : t2);
    int t3 = (int)rintf(v.w * sc); t3 = t3 < -1 ? -1 : (t3 > 1 ? 1 : t3);
    __nv_bfloat162* q2 = (__nv_bfloat162*)(q + (size_t)i * 4);
    q2[0] = __nv_bfloat162(__float2bfloat16_rn((float)t0), __float2bfloat16_rn((float)t1));
    q2[1] = __nv_bfloat162(__float2bfloat16_rn((float)t2), __float2bfloat16_rn((float)t3));
}

// ---------------- rmsnorm + absmax int8 quant, warp-per-row --------------
__global__ __launch_bounds__(256)
void act_quant(const float* __restrict__ xin, int slot) {
    const int lane = threadIdx.x & 31;
    const int wrow = blockIdx.x * 8 + (threadIdx.x >> 5);

    if (slot == 0) {
        const float4* xr = (const float4*)(xin + (size_t)wrow * DIN);
        float4 v[8];
        float ss = 0.f, am = 0.f;
#pragma unroll
        for (int i = 0; i < 8; i++) {
            float4 f = xr[lane + 32 * i];
            v[i] = f;
            ss += f.x * f.x + f.y * f.y + f.z * f.z + f.w * f.w;
            am = fmaxf(am, fmaxf(fmaxf(fabsf(f.x), fabsf(f.y)), fmaxf(fabsf(f.z), fabsf(f.w))));
        }
#pragma unroll
        for (int o = 16; o > 0; o >>= 1) {
            ss += __shfl_xor_sync(0xffffffffu, ss, o);
            am = fmaxf(am, __shfl_xor_sync(0xffffffffu, am, o));
        }
        float rn = rsqrtf(ss / (float)DIN + EPSF);
        float amn = fmaxf(am * rn, EPSF);
        float sc = QBF / amn;
        if (lane == 0) g_sx[wrow] = amn / QBF;

        uint2* qr = (uint2*)(g_xq + (size_t)wrow * DIN);
#pragma unroll
        for (int i = 0; i < 8; i++) {
            float4 f = v[i];
            int t0 = (int)rintf((f.x * rn) * sc); t0 = t0 < -128 ? -128 : (t0 > 127 ? 127 : t0);
            int t1 = (int)rintf((f.y * rn) * sc); t1 = t1 < -128 ? -128 : (t1 > 127 ? 127 : t1);
            int t2 = (int)rintf((f.z * rn) * sc); t2 = t2 < -128 ? -128 : (t2 > 127 ? 127 : t2);
            int t3 = (int)rintf((f.w * rn) * sc); t3 = t3 < -128 ? -128 : (t3 > 127 ? 127 : t3);
            __nv_bfloat162 p0(__float2bfloat16_rn((float)t0), __float2bfloat16_rn((float)t1));
            __nv_bfloat162 p1(__float2bfloat16_rn((float)t2), __float2bfloat16_rn((float)t3));
            uint2 u;
            u.x = *(uint32_t*)&p0;
            u.y = *(uint32_t*)&p1;
            qr[lane + 32 * i] = u;
        }
    } else {
        // single pass: stats come from gemm1 epilogue partials
        float2 s2 = ((const float2*)(g_hss + (size_t)wrow * 64))[lane];
        float2 a2 = ((const float2*)(g_ham + (size_t)wrow * 64))[lane];
        float ss = s2.x + s2.y;
        float am = fmaxf(a2.x, a2.y);
#pragma unroll
        for (int o = 16; o > 0; o >>= 1) {
            ss += __shfl_xor_sync(0xffffffffu, ss, o);
            am = fmaxf(am, __shfl_xor_sync(0xffffffffu, am, o));
        }
        float rn = rsqrtf(ss / (float)INNER + EPSF);
        float amn = fmaxf(am * rn, EPSF);
        float sc = QBF / amn;
        if (lane == 0) g_sh[wrow] = amn / QBF;

        const float4* xr = (const float4*)(g_h + (size_t)wrow * INNER);
        uint2* qr = (uint2*)(g_hq + (size_t)wrow * INNER);
#pragma unroll 4
        for (int i = 0; i < 32; i++) {
            float4 f = xr[lane + 32 * i];
            int t0 = (int)rintf((f.x * rn) * sc); t0 = t0 < -128 ? -128 : (t0 > 127 ? 127 : t0);
            int t1 = (int)rintf((f.y * rn) * sc); t1 = t1 < -128 ? -128 : (t1 > 127 ? 127 : t1);
            int t2 = (int)rintf((f.z * rn) * sc); t2 = t2 < -128 ? -128 : (t2 > 127 ? 127 : t2);
            int t3 = (int)rintf((f.w * rn) * sc); t3 = t3 < -128 ? -128 : (t3 > 127 ? 127 : t3);
            __nv_bfloat162 p0(__float2bfloat16_rn((float)t0), __float2bfloat16_rn((float)t1));
            __nv_bfloat162 p1(__float2bfloat16_rn((float)t2), __float2bfloat16_rn((float)t3));
            uint2 u;
            u.x = *(uint32_t*)&p0;
            u.y = *(uint32_t*)&p1;
            qr[lane + 32 * i] = u;
        }
    }
}

// ---------------- bf16 HMMA GEMM: tile 128x128, 3-stage pipeline ----------
static constexpr int BM = 128, BN = 128, BKE = 64;            // 128 B of K per stage
static constexpr int STAGE_BYTES = (BM + BN) * BKE * 2;       // 32 KB
static constexpr int STAGES = 3;
static constexpr int SMEM_BYTES = STAGES * STAGE_BYTES;       // 96 KB

__global__ __launch_bounds__(256, 2)
void gemm_bf16(const float* __restrict__ bias, float* __restrict__ dout, int layer) {
    const __nv_bfloat16 *A, *B;
    const float* inva;
    float* out;
    int N, K;
    if (layer == 0) { A = g_xq; B = g_w1q; inva = g_sx; out = g_h;  N = INNER; K = DIN;  }
    else            { A = g_hq; B = g_w2q; inva = g_sh; out = dout; N = DIN;   K = INNER; }

    extern __shared__ char smem[];
    const uint32_t sb = smem_u32(smem);

    const int tid = threadIdx.x;
    const int wid = tid >> 5, lid = tid & 31;
    const int wm = wid >> 1, wn = wid & 1;        // 4 x 2 warps, each 32m x 64n
    const int m0 = blockIdx.y * BM;
    const int n0 = blockIdx.x * BN;

    float acc[2][8][4];
#pragma unroll
    for (int i = 0; i < 2; i++)
#pragma unroll
        for (int j = 0; j < 8; j++)
#pragma unroll
            for (int q = 0; q < 4; q++) acc[i][j][q] = 0.f;

    const int nk = K / BKE;

    // ----- precomputed cp.async addressing -----
    const int lrow = tid >> 3;                    // 0..31, +32 per t
    const uint32_t swz0 = (uint32_t)lrow * 128u + (((tid & 7) * 16) ^ ((lrow & 7) << 4));
    const __nv_bfloat16* gA = A + (size_t)(m0 + lrow) * K + (tid & 7) * 8;
    const __nv_bfloat16* gB = B + (size_t)(n0 + lrow) * K + (tid & 7) * 8;

    auto load_stage = [&](int c) {
        uint32_t base = sb + (uint32_t)(c % STAGES) * STAGE_BYTES + swz0;
        const __nv_bfloat16* a = gA + c * BKE;
        const __nv_bfloat16* b = gB + c * BKE;
#pragma unroll
        for (int t = 0; t < 4; t++)
            cp_async16(base + t * 4096u, a + (size_t)t * 32 * K);
#pragma unroll
        for (int t = 0; t < 4; t++)
            cp_async16(base + 16384u + t * 4096u, b + (size_t)t * 32 * K);
        CP_COMMIT();
    };

    // ----- ldmatrix lane addressing -----
    const int ltile = lid >> 3, lr = lid & 7;
    uint32_t a_off[2], a_xor[2];
    const uint32_t a_kadd = (ltile >> 1) * 16;
#pragma unroll
    for (int i = 0; i < 2; i++) {
        uint32_t row = wm * 32 + i * 16 + (ltile & 1) * 8 + lr;
        a_off[i] = row * 128u;
        a_xor[i] = (row & 7u) << 4;
    }
    uint32_t b_off[4], b_xor[4];
    const uint32_t b_kadd = (ltile & 1) * 16;
#pragma unroll
    for (int jb = 0; jb < 4; jb++) {
        uint32_t row = wn * 64 + jb * 16 + (ltile >> 1) * 8 + lr;
        b_off[jb] = row * 128u;
        b_xor[jb] = (row & 7u) << 4;
    }

    load_stage(0);
    load_stage(1);

    for (int c = 0; c < nk; c++) {
        if (c + 1 < nk) { CP_WAIT(1); } else { CP_WAIT(0); }
        __syncthreads();

        uint32_t baseA = sb + (uint32_t)(c % STAGES) * STAGE_BYTES;
        uint32_t baseB = baseA + 16384u;

#pragma unroll
        for (int ks = 0; ks < 4; ks++) {
            uint32_t kbA = ks * 32 + a_kadd;
            uint32_t kbB = ks * 32 + b_kadd;
            uint32_t afr[2][4];
#pragma unroll
            for (int i = 0; i < 2; i++)
                ldmx4(afr[i][0], afr[i][1], afr[i][2], afr[i][3],
                      baseA + a_off[i] + (kbA ^ a_xor[i]));
            uint32_t bfr[8][2];
#pragma unroll
            for (int jb = 0; jb < 4; jb++) {
                uint32_t r0, r1, r2, r3;
                ldmx4(r0, r1, r2, r3, baseB + b_off[jb] + (kbB ^ b_xor[jb]));
                bfr[jb * 2 + 0][0] = r0; bfr[jb * 2 + 0][1] = r1;
                bfr[jb * 2 + 1][0] = r2; bfr[jb * 2 + 1][1] = r3;
            }
#pragma unroll
            for (int i = 0; i < 2; i++)
#pragma unroll
                for (int j = 0; j < 8; j++)
                    mma_bf16(acc[i][j], afr[i], bfr[j]);
        }

        if (c + 2 < nk) load_stage(c + 2);
    }

    // ----- epilogue -----
    const float fw = g_wfac[layer];
    const int g = lid >> 2, tig = lid & 3;
    const int tile64 = blockIdx.x * 2 + wn;       // 64-col tile index (layer 0 stats)
#pragma unroll
    for (int i = 0; i < 2; i++) {
        int r0 = m0 + wm * 32 + i * 16 + g;
        float fa0 = inva[r0] * fw;
        float fa1 = inva[r0 + 8] * fw;
        float ssa = 0.f, ama = 0.f, ssb = 0.f, amb = 0.f;
#pragma unroll
        for (int j = 0; j < 8; j++) {
            int n = n0 + wn * 64 + j * 8 + tig * 2;
            float bx = bias[n], by = bias[n + 1];
            float v0 = acc[i][j][0] * fa0 + bx;
            float v1 = acc[i][j][1] * fa0 + by;
            float v2 = acc[i][j][2] * fa1 + bx;
            float v3 = acc[i][j][3] * fa1 + by;
            if (layer == 0) {
                v0 = 0.5f * v0 * (1.f + erff(v0 * 0.70710678118654752f));
                v1 = 0.5f * v1 * (1.f + erff(v1 * 0.70710678118654752f));
                v2 = 0.5f * v2 * (1.f + erff(v2 * 0.70710678118654752f));
                v3 = 0.5f * v3 * (1.f + erff(v3 * 0.70710678118654752f));
                ssa += v0 * v0 + v1 * v1;
                ssb += v2 * v2 + v3 * v3;
                ama = fmaxf(ama, fmaxf(fabsf(v0), fabsf(v1)));
                amb = fmaxf(amb, fmaxf(fabsf(v2), fabsf(v3)));
            }
            *(float2*)(out + (size_t)r0 * N + n)       = make_float2(v0, v1);
            *(float2*)(out + (size_t)(r0 + 8) * N + n) = make_float2(v2, v3);
        }
        if (layer == 0) {
            // quad reduce over tig (lanes g*4 .. g*4+3)
#pragma unroll
            for (int o = 1; o < 4; o <<= 1) {
                ssa += __shfl_xor_sync(0xffffffffu, ssa, o);
                ssb += __shfl_xor_sync(0xffffffffu, ssb, o);
                ama = fmaxf(ama, __shfl_xor_sync(0xffffffffu, ama, o));
                amb = fmaxf(amb, __shfl_xor_sync(0xffffffffu, amb, o));
            }
            if (tig == 0) {
                g_hss[(size_t)r0 * 64 + tile64]       = ssa;
                g_ham[(size_t)r0 * 64 + tile64]       = ama;
                g_hss[(size_t)(r0 + 8) * 64 + tile64] = ssb;
                g_ham[(size_t)(r0 + 8) * 64 + tile64] = amb;
            }
        }
    }
}

// -------------------------------------------------------------------------
extern "C" void kernel_launch(void* const* d_in, const int* in_sizes, int n_in,
                              void* d_out, int out_size) {
    const float* x  = (const float*)d_in[0];
    const float* w1 = (const float*)d_in[1];
    const float* b1 = (const float*)d_in[2];
    const float* w2 = (const float*)d_in[3];
    const float* b2 = (const float*)d_in[4];
    float* out = (float*)d_out;

    const int n = INNER * DIN;

    cudaFuncSetAttribute(gemm_bf16, cudaFuncAttributeMaxDynamicSharedMemorySize, SMEM_BYTES);

    wabs_part<<<dim3(256, 2), 256>>>(w1, w2, n);                 // 0
    wquant<<<dim3(n / 4 / 256, 2), 256>>>(w1, w2, n);            // 1
    act_quant<<<MTOK / 8, 256>>>(x, 0);                          // 2
    gemm_bf16<<<dim3(INNER / BN, MTOK / BM), 256, SMEM_BYTES>>>(b1, nullptr, 0);  // 3
    act_quant<<<MTOK / 8, 256>>>(nullptr, 1);                    // 4
    gemm_bf16<<<dim3(DIN / BN, MTOK / BM), 256, SMEM_BYTES>>>(b2, out, 1);        // 5
}